// round 9
// baseline (speedup 1.0000x reference)
#include <cuda_runtime.h>
#include <cuda_bf16.h>
#include <stdint.h>
#include <math.h>

#define Bsz   2
#define Slen  2048
#define Hdim  1024
#define NHn   16
#define HDn   64
#define Mtot  (Bsz*Slen)
#define EPSf  1e-12f

// int8 quantization: x = (q1*128 + q0) * delta ; 1/dx = 2560 (acts+ctx), 1/dw = 65536 (weights)
#define SC_X  2560.f
#define SC_W  65536.f
#define DQ_S1 (16384.f / (SC_X * SC_W))   // 2^14 * dx * dw
#define DQ_S2 (128.f   / (SC_X * SC_W))   // 2^7  * dx * dw

// -------- scratch (no allocations allowed) --------
__device__ float g_y[Mtot*Hdim];
__device__ char g_xq1[Mtot*Hdim], g_xq0[Mtot*Hdim];
__device__ char g_wq1[4*Hdim*Hdim], g_wq0[4*Hdim*Hdim];
__device__ char g_cq1[Mtot*Hdim], g_cq0[Mtot*Hdim];
__device__ __nv_bfloat16 g_qh[Mtot*Hdim], g_ql[Mtot*Hdim];
__device__ __nv_bfloat16 g_kh[Mtot*Hdim], g_kl[Mtot*Hdim];
__device__ __nv_bfloat16 g_vh[Mtot*Hdim], g_vl[Mtot*Hdim];

// ---------------- helpers ----------------
__device__ __forceinline__ uint32_t smem_u32(const void* p) {
    uint32_t a;
    asm("{ .reg .u64 t; cvta.to.shared.u64 t, %1; cvt.u32.u64 %0, t; }" : "=r"(a) : "l"(p));
    return a;
}
__device__ __forceinline__ void cp16(uint32_t dst, const void* src) {
    asm volatile("cp.async.cg.shared.global [%0], [%1], 16;" :: "r"(dst), "l"(src));
}
#define CP_COMMIT() asm volatile("cp.async.commit_group;")
#define CP_WAIT(n)  asm volatile("cp.async.wait_group %0;" :: "n"(n))
#define LDSM_X4(r0,r1,r2,r3,addr) \
    asm volatile("ldmatrix.sync.aligned.m8n8.x4.shared.b16 {%0,%1,%2,%3}, [%4];" \
        : "=r"(r0),"=r"(r1),"=r"(r2),"=r"(r3) : "r"(addr))
#define LDSM_X4_T(r0,r1,r2,r3,addr) \
    asm volatile("ldmatrix.sync.aligned.m8n8.x4.trans.shared.b16 {%0,%1,%2,%3}, [%4];" \
        : "=r"(r0),"=r"(r1),"=r"(r2),"=r"(r3) : "r"(addr))
#define MMA16816(c, a, b) \
    asm volatile("mma.sync.aligned.m16n8k16.row.col.f32.bf16.bf16.f32 " \
        "{%0,%1,%2,%3}, {%4,%5,%6,%7}, {%8,%9}, {%0,%1,%2,%3};" \
        : "+f"((c)[0]),"+f"((c)[1]),"+f"((c)[2]),"+f"((c)[3]) \
        : "r"((a)[0]),"r"((a)[1]),"r"((a)[2]),"r"((a)[3]), "r"((b)[0]),"r"((b)[1]))
#define MMAI(c, a, b) \
    asm volatile("mma.sync.aligned.m16n8k32.row.col.s32.s8.s8.s32 " \
        "{%0,%1,%2,%3}, {%4,%5,%6,%7}, {%8,%9}, {%0,%1,%2,%3};" \
        : "+r"((c)[0]),"+r"((c)[1]),"+r"((c)[2]),"+r"((c)[3]) \
        : "r"((a)[0]),"r"((a)[1]),"r"((a)[2]),"r"((a)[3]), "r"((b)[0]),"r"((b)[1]))

__device__ __forceinline__ uint32_t pk_bf16x2(float lo, float hi) {
    uint32_t r;
    asm("cvt.rn.bf16x2.f32 %0, %1, %2;" : "=r"(r) : "f"(hi), "f"(lo));
    return r;
}
__device__ __forceinline__ void quant_split(float v, float sc, float cl, int& a, int& b) {
    int q = __float2int_rn(fminf(fmaxf(v, -cl), cl) * sc);
    a = (q + 64) >> 7;
    b = q - (a << 7);
}

// ---------------- quantize fp32 -> int8 (q1,q0) ----------------
__global__ void quant_kernel(const float* __restrict__ src, char* __restrict__ o1,
                             char* __restrict__ o0, float sc, float cl) {
    int i = blockIdx.x * 256 + threadIdx.x;
    float4 v = ((const float4*)src)[i];
    int a0, b0, a1, b1, a2, b2, a3, b3;
    quant_split(v.x, sc, cl, a0, b0);
    quant_split(v.y, sc, cl, a1, b1);
    quant_split(v.z, sc, cl, a2, b2);
    quant_split(v.w, sc, cl, a3, b3);
    ((char4*)o1)[i] = make_char4((char)a0, (char)a1, (char)a2, (char)a3);
    ((char4*)o0)[i] = make_char4((char)b0, (char)b1, (char)b2, (char)b3);
}

// ---------------- int8 GEMM core, cp.async 2-stage, BK=64 ----------------
// smem/stage: 4 tensors x 128 rows x 80B (64B data + 16B pad) = 40960 B
#define LDB 80
#define GI_TEN 10240
#define GI_STG 40960

__device__ __forceinline__ void gemm_core_i8(
    uint32_t sbase,
    const char* __restrict__ A1, const char* __restrict__ A0,
    const char* __restrict__ W1, const char* __restrict__ W0,
    int m0, int n0, int c11[4][4][4], int ccr[4][4][4])
{
    const int tid = threadIdx.x, wid = tid >> 5, lane = tid & 31;
    const int wm0 = (wid & 1) * 64, wn0 = (wid >> 1) * 32;
    const int a_row = wm0 + (lane & 15);
    const int b_row = wn0 + (lane & 7) + ((lane >> 4) << 3);
    const int a_cb = (lane >> 4) * 16;          // byte offset within 32B k-step
    const int b_cb = ((lane >> 3) & 1) * 16;

#define GI_LOAD(st, k0) do { \
        const uint32_t sb_ = sbase + (st) * GI_STG; \
        _Pragma("unroll") \
        for (int i_ = 0; i_ < 2; i_++) { \
            const int u_ = i_ * 256 + tid; \
            const int r_ = u_ >> 2, c_ = (u_ & 3) * 16; \
            const uint32_t off_ = (uint32_t)(r_ * LDB + c_); \
            const size_t ga_ = (size_t)(m0 + r_) * Hdim + (k0) + c_; \
            const size_t gb_ = (size_t)(n0 + r_) * Hdim + (k0) + c_; \
            cp16(sb_ + off_,               A1 + ga_); \
            cp16(sb_ + GI_TEN + off_,      A0 + ga_); \
            cp16(sb_ + 2 * GI_TEN + off_,  W1 + gb_); \
            cp16(sb_ + 3 * GI_TEN + off_,  W0 + gb_); \
        } } while (0)

    GI_LOAD(0, 0);
    CP_COMMIT();

    for (int it = 0; it < 16; it++) {
        if (it < 15) {
            GI_LOAD((it + 1) & 1, (it + 1) * 64);
            CP_COMMIT();
            CP_WAIT(1);
        } else {
            CP_WAIT(0);
        }
        __syncthreads();

        const uint32_t sb = sbase + (it & 1) * GI_STG;
        const uint32_t aA1 = sb, aA0 = sb + GI_TEN;
        const uint32_t aW1 = sb + 2 * GI_TEN, aW0 = sb + 3 * GI_TEN;

#pragma unroll
        for (int ks = 0; ks < 2; ks++) {
            const int kb = ks * 32;
            uint32_t aq1[4][4], aq0[4][4];
#pragma unroll
            for (int mf = 0; mf < 4; mf++) {
                const uint32_t off = (uint32_t)((a_row + mf * 16) * LDB + kb + a_cb);
                LDSM_X4(aq1[mf][0], aq1[mf][1], aq1[mf][2], aq1[mf][3], aA1 + off);
                LDSM_X4(aq0[mf][0], aq0[mf][1], aq0[mf][2], aq0[mf][3], aA0 + off);
            }
#pragma unroll
            for (int nfp = 0; nfp < 2; nfp++) {
                const uint32_t off = (uint32_t)((b_row + nfp * 16) * LDB + kb + b_cb);
                uint32_t br1[4], br0[4];
                LDSM_X4(br1[0], br1[1], br1[2], br1[3], aW1 + off);
                LDSM_X4(br0[0], br0[1], br0[2], br0[3], aW0 + off);
#pragma unroll
                for (int mf = 0; mf < 4; mf++) {
#pragma unroll
                    for (int hf = 0; hf < 2; hf++) {
                        MMAI(c11[mf][nfp * 2 + hf], aq1[mf], br1 + hf * 2);
                        MMAI(ccr[mf][nfp * 2 + hf], aq1[mf], br0 + hf * 2);
                        MMAI(ccr[mf][nfp * 2 + hf], aq0[mf], br1 + hf * 2);
                    }
                }
            }
        }
        __syncthreads();
    }
#undef GI_LOAD
}

// ---- fused QKV projection (int8 core): N stacked 3072 -> bf16 hi/lo head layout ----
__global__ void __launch_bounds__(256, 1) gemm_qkv(
    const char* __restrict__ A1, const char* __restrict__ A0,
    const char* __restrict__ W1, const char* __restrict__ W0,
    const float* __restrict__ bq, const float* __restrict__ bk, const float* __restrict__ bv,
    __nv_bfloat16* __restrict__ qh, __nv_bfloat16* __restrict__ ql,
    __nv_bfloat16* __restrict__ kh, __nv_bfloat16* __restrict__ kl,
    __nv_bfloat16* __restrict__ vh, __nv_bfloat16* __restrict__ vl)
{
    extern __shared__ char dsm[];
    const uint32_t sbase = smem_u32(dsm);
    const int tid = threadIdx.x, wid = tid >> 5, lane = tid & 31;
    const int n0 = blockIdx.x * 128, m0 = blockIdx.y * 128;

    int c11[4][4][4], ccr[4][4][4];
#pragma unroll
    for (int i = 0; i < 4; i++)
#pragma unroll
        for (int j = 0; j < 4; j++)
#pragma unroll
            for (int v = 0; v < 4; v++) { c11[i][j][v] = 0; ccr[i][j][v] = 0; }

    gemm_core_i8(sbase, A1, A0, W1, W0, m0, n0, c11, ccr);

    const int proj = n0 >> 10;
    const float* bias = (proj == 0) ? bq : (proj == 1) ? bk : bv;
    __nv_bfloat16* outH = (proj == 0) ? qh : (proj == 1) ? kh : vh;
    __nv_bfloat16* outL = (proj == 0) ? ql : (proj == 1) ? kl : vl;

    const int wm0 = (wid & 1) * 64, wn0 = (wid >> 1) * 32;
    const int rbase = m0 + wm0 + (lane >> 2);
    const int cbase = n0 + wn0 + (lane & 3) * 2;
#pragma unroll
    for (int mf = 0; mf < 4; mf++) {
#pragma unroll
        for (int nf = 0; nf < 4; nf++) {
#pragma unroll
            for (int half = 0; half < 2; half++) {
                const int r = rbase + mf * 16 + half * 8;
                const int c = cbase + nf * 8;
                const int np = c & 1023;
                float v0 = fmaf((float)c11[mf][nf][half*2+0], DQ_S1,
                          fmaf((float)ccr[mf][nf][half*2+0], DQ_S2, bias[np]));
                float v1 = fmaf((float)c11[mf][nf][half*2+1], DQ_S1,
                          fmaf((float)ccr[mf][nf][half*2+1], DQ_S2, bias[np+1]));
                const int b = r >> 11, s = r & (Slen - 1);
                const int h = np >> 6, d = np & 63;
                const size_t idx = (((size_t)(b * NHn + h) * Slen) + s) * HDn + d;
                __nv_bfloat16 h0 = __float2bfloat16(v0);
                __nv_bfloat16 h1 = __float2bfloat16(v1);
                *(uint32_t*)(outH + idx) =
                    ((uint32_t)__bfloat16_as_ushort(h1) << 16) | __bfloat16_as_ushort(h0);
                *(uint32_t*)(outL + idx) =
                    pk_bf16x2(v0 - __bfloat162float(h0), v1 - __bfloat162float(h1));
            }
        }
    }
}

// ---- output projection (int8 core): fp32 + bias + residual ----
__global__ void __launch_bounds__(256, 1) gemm_out(
    const char* __restrict__ A1, const char* __restrict__ A0,
    const char* __restrict__ W1, const char* __restrict__ W0,
    const float* __restrict__ bias, const float* __restrict__ res, float* __restrict__ out)
{
    extern __shared__ char dsm[];
    const uint32_t sbase = smem_u32(dsm);
    const int tid = threadIdx.x, wid = tid >> 5, lane = tid & 31;
    const int n0 = blockIdx.x * 128, m0 = blockIdx.y * 128;

    int c11[4][4][4], ccr[4][4][4];
#pragma unroll
    for (int i = 0; i < 4; i++)
#pragma unroll
        for (int j = 0; j < 4; j++)
#pragma unroll
            for (int v = 0; v < 4; v++) { c11[i][j][v] = 0; ccr[i][j][v] = 0; }

    gemm_core_i8(sbase, A1, A0, W1, W0, m0, n0, c11, ccr);

    const int wm0 = (wid & 1) * 64, wn0 = (wid >> 1) * 32;
    const int rbase = m0 + wm0 + (lane >> 2);
    const int cbase = n0 + wn0 + (lane & 3) * 2;
#pragma unroll
    for (int mf = 0; mf < 4; mf++) {
#pragma unroll
        for (int nf = 0; nf < 4; nf++) {
#pragma unroll
            for (int half = 0; half < 2; half++) {
                const int r = rbase + mf * 16 + half * 8;
                const int c = cbase + nf * 8;
                const size_t idx = (size_t)r * Hdim + c;
                float2 rv = *(const float2*)(res + idx);
                float2 o;
                o.x = fmaf((float)c11[mf][nf][half*2+0], DQ_S1,
                      fmaf((float)ccr[mf][nf][half*2+0], DQ_S2, bias[c] + rv.x));
                o.y = fmaf((float)c11[mf][nf][half*2+1], DQ_S1,
                      fmaf((float)ccr[mf][nf][half*2+1], DQ_S2, bias[c+1] + rv.y));
                *(float2*)(out + idx) = o;
            }
        }
    }
}

// ---------------- MMA flash attention (bf16x3), causal, cp.async 2-stage K/V ----------------
#define ALD 72
#define A_TEN 9216
#define A_STG 36864
__global__ void __launch_bounds__(128) attn_mma(
    const __nv_bfloat16* __restrict__ Qh, const __nv_bfloat16* __restrict__ Ql,
    const __nv_bfloat16* __restrict__ Kh, const __nv_bfloat16* __restrict__ Kl,
    const __nv_bfloat16* __restrict__ Vh, const __nv_bfloat16* __restrict__ Vl,
    char* __restrict__ Cq1, char* __restrict__ Cq0)
{
    extern __shared__ char dsm[];
    const uint32_t sbase = smem_u32(dsm);
    const int tid = threadIdx.x, wid = tid >> 5, lane = tid & 31;
    const int qt = blockIdx.x, h = blockIdx.y, b = blockIdx.z;
    const int m0 = qt * 64, wq0 = wid * 16;
    const size_t base = (size_t)(b * NHn + h) * Slen * HDn;

    // ---- stage Q hi/lo into stage0 regions ----
    {
        const __nv_bfloat16* srcH = Qh + base + (size_t)m0 * HDn;
        const __nv_bfloat16* srcL = Ql + base + (size_t)m0 * HDn;
#pragma unroll
        for (int i = 0; i < 4; i++) {
            int u = i * 128 + tid, r = u >> 3, c = u & 7;
            int cs = c ^ ((r & 3) << 1);
            int so = (r * ALD + cs * 8) * 2, go = r * 64 + c * 8;
            *(uint4*)(dsm + so) = *(const uint4*)(srcH + go);
            *(uint4*)(dsm + A_TEN + so) = *(const uint4*)(srcL + go);
        }
    }
    __syncthreads();

    const int rA = (lane & 7) + ((lane >> 3) & 1) * 8;
    const int cA = (lane >> 4) & 1;
    const int rB = (lane & 7) + ((lane >> 4) << 3);
    const int cB = (lane >> 3) & 1;
    const int swzA = (rA & 3) << 1;
    const int swzB = (rB & 3) << 1;

    uint32_t qfh[4][4], qfl[4][4];
    {
        const int row = wq0 + rA;
        const uint32_t rb = (uint32_t)(row * (ALD * 2));
        const int swz = (row & 3) << 1;
#pragma unroll
        for (int kb = 0; kb < 4; kb++) {
            const uint32_t off = rb + (uint32_t)(((2 * kb + cA) ^ swz) * 16);
            LDSM_X4(qfh[kb][0], qfh[kb][1], qfh[kb][2], qfh[kb][3], sbase + off);
            LDSM_X4(qfl[kb][0], qfl[kb][1], qfl[kb][2], qfl[kb][3], sbase + A_TEN + off);
        }
    }
    __syncthreads();

#define A_LOAD(st, k0) do { \
        const uint32_t sb_ = sbase + (st) * A_STG; \
        const __nv_bfloat16* k0p_ = Kh + base + (size_t)(k0) * HDn; \
        const __nv_bfloat16* k1p_ = Kl + base + (size_t)(k0) * HDn; \
        const __nv_bfloat16* v0p_ = Vh + base + (size_t)(k0) * HDn; \
        const __nv_bfloat16* v1p_ = Vl + base + (size_t)(k0) * HDn; \
        _Pragma("unroll") \
        for (int i_ = 0; i_ < 4; i_++) { \
            int u_ = i_ * 128 + tid, r_ = u_ >> 3, c_ = u_ & 7; \
            int cs_ = c_ ^ ((r_ & 3) << 1); \
            uint32_t so_ = (uint32_t)((r_ * ALD + cs_ * 8) * 2); \
            int go_ = r_ * 64 + c_ * 8; \
            cp16(sb_ + so_,             k0p_ + go_); \
            cp16(sb_ + A_TEN + so_,     k1p_ + go_); \
            cp16(sb_ + 2 * A_TEN + so_, v0p_ + go_); \
            cp16(sb_ + 3 * A_TEN + so_, v1p_ + go_); \
        } } while (0)

    A_LOAD(0, 0);
    CP_COMMIT();

    float o[8][4];
#pragma unroll
    for (int i = 0; i < 8; i++)
#pragma unroll
        for (int v = 0; v < 4; v++) o[i][v] = 0.f;
    float mr0 = -1e30f, mr1 = -1e30f, lr0 = 0.f, lr1 = 0.f;

    for (int kt = 0; kt <= qt; kt++) {
        if (kt < qt) {
            A_LOAD((kt + 1) & 1, (kt + 1) * 64);
            CP_COMMIT();
            CP_WAIT(1);
        } else {
            CP_WAIT(0);
        }
        __syncthreads();

        const uint32_t sb = sbase + (kt & 1) * A_STG;
        const uint32_t aKh = sb, aKl = sb + A_TEN;
        const uint32_t aVh = sb + 2 * A_TEN, aVl = sb + 3 * A_TEN;

        float s[8][4];
#pragma unroll
        for (int i = 0; i < 8; i++)
#pragma unroll
            for (int v = 0; v < 4; v++) s[i][v] = 0.f;
#pragma unroll
        for (int kb = 0; kb < 4; kb++) {
#pragma unroll
            for (int np = 0; np < 4; np++) {
                const int row = np * 16 + rB;
                const uint32_t off = (uint32_t)(row * (ALD * 2) + (((2 * kb + cB) ^ swzB)) * 16);
                uint32_t kh[4], kl[4];
                LDSM_X4(kh[0], kh[1], kh[2], kh[3], aKh + off);
                LDSM_X4(kl[0], kl[1], kl[2], kl[3], aKl + off);
                MMA16816(s[2*np],   qfh[kb], kh);     MMA16816(s[2*np],   qfh[kb], kl);
                MMA16816(s[2*np],   qfl[kb], kh);
                MMA16816(s[2*np+1], qfh[kb], kh + 2); MMA16816(s[2*np+1], qfh[kb], kl + 2);
                MMA16816(s[2*np+1], qfl[kb], kh + 2);
            }
        }

#pragma unroll
        for (int nf = 0; nf < 8; nf++)
#pragma unroll
            for (int v = 0; v < 4; v++) s[nf][v] *= 0.125f;
        if (kt == qt) {
            const int row0 = wq0 + (lane >> 2), row1 = row0 + 8;
            const int colb = (lane & 3) * 2;
#pragma unroll
            for (int nf = 0; nf < 8; nf++) {
                const int c0 = nf * 8 + colb, c1 = c0 + 1;
                if (c0 > row0) s[nf][0] = -1e30f;
                if (c1 > row0) s[nf][1] = -1e30f;
                if (c0 > row1) s[nf][2] = -1e30f;
                if (c1 > row1) s[nf][3] = -1e30f;
            }
        }

        float mx0 = s[0][0], mx1 = s[0][2];
#pragma unroll
        for (int nf = 0; nf < 8; nf++) {
            mx0 = fmaxf(mx0, fmaxf(s[nf][0], s[nf][1]));
            mx1 = fmaxf(mx1, fmaxf(s[nf][2], s[nf][3]));
        }
        mx0 = fmaxf(mx0, __shfl_xor_sync(0xffffffffu, mx0, 1));
        mx0 = fmaxf(mx0, __shfl_xor_sync(0xffffffffu, mx0, 2));
        mx1 = fmaxf(mx1, __shfl_xor_sync(0xffffffffu, mx1, 1));
        mx1 = fmaxf(mx1, __shfl_xor_sync(0xffffffffu, mx1, 2));
        const float nm0 = fmaxf(mr0, mx0), nm1 = fmaxf(mr1, mx1);
        const float cr0 = __expf(mr0 - nm0), cr1 = __expf(mr1 - nm1);
        lr0 *= cr0; lr1 *= cr1;
#pragma unroll
        for (int nf = 0; nf < 8; nf++) {
            o[nf][0] *= cr0; o[nf][1] *= cr0;
            o[nf][2] *= cr1; o[nf][3] *= cr1;
        }
        mr0 = nm0; mr1 = nm1;

        uint32_t ph[8], phb[8], pl[8], plb[8];
#pragma unroll
        for (int nf = 0; nf < 8; nf++) {
            float p0 = __expf(s[nf][0] - nm0), p1 = __expf(s[nf][1] - nm0);
            float p2 = __expf(s[nf][2] - nm1), p3 = __expf(s[nf][3] - nm1);
            lr0 += p0 + p1; lr1 += p2 + p3;
            ph[nf]  = pk_bf16x2(p0, p1);
            phb[nf] = pk_bf16x2(p2, p3);
            float h0 = __uint_as_float(ph[nf] << 16);
            float h1 = __uint_as_float(ph[nf] & 0xFFFF0000u);
            float h2 = __uint_as_float(phb[nf] << 16);
            float h3 = __uint_as_float(phb[nf] & 0xFFFF0000u);
            pl[nf]  = pk_bf16x2(p0 - h0, p1 - h1);
            plb[nf] = pk_bf16x2(p2 - h2, p3 - h3);
        }

#pragma unroll
        for (int kb = 0; kb < 4; kb++) {
            uint32_t pah[4] = { ph[2*kb], phb[2*kb], ph[2*kb+1], phb[2*kb+1] };
            uint32_t pal[4] = { pl[2*kb], plb[2*kb], pl[2*kb+1], plb[2*kb+1] };
            const int row = kb * 16 + rA;
            const uint32_t rb = (uint32_t)(row * (ALD * 2));
#pragma unroll
            for (int np = 0; np < 4; np++) {
                const uint32_t off = rb + (uint32_t)(((2 * np + cA) ^ swzA) * 16);
                uint32_t vh[4], vl[4];
                LDSM_X4_T(vh[0], vh[1], vh[2], vh[3], aVh + off);
                LDSM_X4_T(vl[0], vl[1], vl[2], vl[3], aVl + off);
                MMA16816(o[2*np],   pah, vh);     MMA16816(o[2*np],   pah, vl);
                MMA16816(o[2*np],   pal, vh);
                MMA16816(o[2*np+1], pah, vh + 2); MMA16816(o[2*np+1], pah, vl + 2);
                MMA16816(o[2*np+1], pal, vh + 2);
            }
        }
        __syncthreads();
    }
#undef A_LOAD

    lr0 += __shfl_xor_sync(0xffffffffu, lr0, 1);
    lr0 += __shfl_xor_sync(0xffffffffu, lr0, 2);
    lr1 += __shfl_xor_sync(0xffffffffu, lr1, 1);
    lr1 += __shfl_xor_sync(0xffffffffu, lr1, 2);
    const float iv0 = 1.f / lr0, iv1 = 1.f / lr1;

    const int s0 = m0 + wq0 + (lane >> 2), s1 = s0 + 8;
    const size_t rb0 = (size_t)(b * Slen + s0) * Hdim + h * 64;
    const size_t rb1 = (size_t)(b * Slen + s1) * Hdim + h * 64;
#pragma unroll
    for (int nf = 0; nf < 8; nf++) {
        const int col = nf * 8 + (lane & 3) * 2;
        float v0 = o[nf][0] * iv0, v1 = o[nf][1] * iv0;
        float v2 = o[nf][2] * iv1, v3 = o[nf][3] * iv1;
        int a0, b0, a1, b1, a2, b2, a3, b3;
        quant_split(v0, SC_X, 6.3f, a0, b0);
        quant_split(v1, SC_X, 6.3f, a1, b1);
        quant_split(v2, SC_X, 6.3f, a2, b2);
        quant_split(v3, SC_X, 6.3f, a3, b3);
        *(char2*)(Cq1 + rb0 + col) = make_char2((char)a0, (char)a1);
        *(char2*)(Cq0 + rb0 + col) = make_char2((char)b0, (char)b1);
        *(char2*)(Cq1 + rb1 + col) = make_char2((char)a2, (char)a3);
        *(char2*)(Cq0 + rb1 + col) = make_char2((char)b2, (char)b3);
    }
}

// ---------------- LayerNorm ----------------
__global__ void ln_kernel(const float* __restrict__ y, const float* __restrict__ g,
                          const float* __restrict__ be, float* __restrict__ out)
{
    __shared__ float red[256];
    const int row = blockIdx.x, tid = threadIdx.x;
    const float4 v = ((const float4*)(y + (size_t)row * Hdim))[tid];
    float sum = v.x + v.y + v.z + v.w;
    red[tid] = sum; __syncthreads();
    for (int s = 128; s > 0; s >>= 1) { if (tid < s) red[tid] += red[tid + s]; __syncthreads(); }
    const float mu = red[0] * (1.f / 1024.f);
    __syncthreads();
    const float d0 = v.x - mu, d1 = v.y - mu, d2 = v.z - mu, d3 = v.w - mu;
    red[tid] = d0 * d0 + d1 * d1 + d2 * d2 + d3 * d3; __syncthreads();
    for (int s = 128; s > 0; s >>= 1) { if (tid < s) red[tid] += red[tid + s]; __syncthreads(); }
    const float inv = rsqrtf(red[0] * (1.f / 1024.f) + EPSf);
    const float4 gg = ((const float4*)g)[tid];
    const float4 bb = ((const float4*)be)[tid];
    float4 o;
    o.x = d0 * inv * gg.x + bb.x;
    o.y = d1 * inv * gg.y + bb.y;
    o.z = d2 * inv * gg.z + bb.z;
    o.w = d3 * inv * gg.w + bb.w;
    ((float4*)(out + (size_t)row * Hdim))[tid] = o;
}

// ---------------- launch ----------------
extern "C" void kernel_launch(void* const* d_in, const int* in_sizes, int n_in,
                              void* d_out, int out_size)
{
    const float* x    = (const float*)d_in[0];
    const float* Wq   = (const float*)d_in[1];
    const float* bq   = (const float*)d_in[2];
    const float* Wk   = (const float*)d_in[3];
    const float* bk   = (const float*)d_in[4];
    const float* Wv   = (const float*)d_in[5];
    const float* bv   = (const float*)d_in[6];
    const float* Wo   = (const float*)d_in[7];
    const float* bo   = (const float*)d_in[8];
    const float* ln_g = (const float*)d_in[9];
    const float* ln_b = (const float*)d_in[10];
    float* out = (float*)d_out;

    float* yp;
    char *xq1, *xq0, *wq1, *wq0, *cq1, *cq0;
    __nv_bfloat16 *qh, *ql, *kh, *kl, *vh, *vl;
    cudaGetSymbolAddress((void**)&yp, g_y);
    cudaGetSymbolAddress((void**)&xq1, g_xq1);
    cudaGetSymbolAddress((void**)&xq0, g_xq0);
    cudaGetSymbolAddress((void**)&wq1, g_wq1);
    cudaGetSymbolAddress((void**)&wq0, g_wq0);
    cudaGetSymbolAddress((void**)&cq1, g_cq1);
    cudaGetSymbolAddress((void**)&cq0, g_cq0);
    cudaGetSymbolAddress((void**)&qh, g_qh);
    cudaGetSymbolAddress((void**)&ql, g_ql);
    cudaGetSymbolAddress((void**)&kh, g_kh);
    cudaGetSymbolAddress((void**)&kl, g_kl);
    cudaGetSymbolAddress((void**)&vh, g_vh);
    cudaGetSymbolAddress((void**)&vl, g_vl);

    static bool attr_done = false;
    if (!attr_done) {
        cudaFuncSetAttribute(gemm_qkv, cudaFuncAttributeMaxDynamicSharedMemorySize, 2 * GI_STG);
        cudaFuncSetAttribute(gemm_out, cudaFuncAttributeMaxDynamicSharedMemorySize, 2 * GI_STG);
        cudaFuncSetAttribute(attn_mma, cudaFuncAttributeMaxDynamicSharedMemorySize, 2 * A_STG);
        attr_done = true;
    }

    const int WSZ = Hdim * Hdim;
    quant_kernel<<<Mtot * Hdim / 1024, 256>>>(x, xq1, xq0, SC_X, 6.3f);
    quant_kernel<<<WSZ / 1024, 256>>>(Wq, wq1 + 0 * WSZ, wq0 + 0 * WSZ, SC_W, 0.24f);
    quant_kernel<<<WSZ / 1024, 256>>>(Wk, wq1 + 1 * WSZ, wq0 + 1 * WSZ, SC_W, 0.24f);
    quant_kernel<<<WSZ / 1024, 256>>>(Wv, wq1 + 2 * WSZ, wq0 + 2 * WSZ, SC_W, 0.24f);
    quant_kernel<<<WSZ / 1024, 256>>>(Wo, wq1 + 3 * WSZ, wq0 + 3 * WSZ, SC_W, 0.24f);

    gemm_qkv<<<dim3(3 * Hdim / 128, Mtot / 128), 256, 2 * GI_STG>>>(
        xq1, xq0, wq1, wq0, bq, bk, bv, qh, ql, kh, kl, vh, vl);

    attn_mma<<<dim3(Slen / 64, NHn, Bsz), 128, 2 * A_STG>>>(qh, ql, kh, kl, vh, vl, cq1, cq0);

    gemm_out<<<dim3(Hdim / 128, Mtot / 128), 256, 2 * GI_STG>>>(
        cq1, cq0, wq1 + 3 * WSZ, wq0 + 3 * WSZ, bo, x, yp);

    ln_kernel<<<Mtot, 256>>>(yp, ln_g, ln_b, out);
}

// round 10
// speedup vs baseline: 2.6629x; 2.6629x over previous
#include <cuda_runtime.h>
#include <cuda_fp16.h>
#include <stdint.h>
#include <math.h>

#define Bsz   2
#define Slen  2048
#define Hdim  1024
#define NHn   16
#define HDn   64
#define Mtot  (Bsz*Slen)
#define EPSf  1e-12f
#define WSCL  256.f
#define WDSC  (1.f/256.f)

// -------- scratch (no allocations allowed) --------
__device__ float g_y[Mtot*Hdim];
__device__ __half g_xh[Mtot*Hdim];
__device__ __half g_wh[4*Hdim*Hdim], g_wl[4*Hdim*Hdim];
__device__ __half g_qh[Mtot*Hdim];
__device__ __half g_kh[Mtot*Hdim], g_kl[Mtot*Hdim];
__device__ __half g_vh[Mtot*Hdim], g_vl[Mtot*Hdim];
__device__ __half g_ch[Mtot*Hdim];

// ---------------- helpers ----------------
__device__ __forceinline__ uint32_t smem_u32(const void* p) {
    uint32_t a;
    asm("{ .reg .u64 t; cvta.to.shared.u64 t, %1; cvt.u32.u64 %0, t; }" : "=r"(a) : "l"(p));
    return a;
}
__device__ __forceinline__ void cp16(uint32_t dst, const void* src) {
    asm volatile("cp.async.cg.shared.global [%0], [%1], 16;" :: "r"(dst), "l"(src));
}
#define CP_COMMIT() asm volatile("cp.async.commit_group;")
#define CP_WAIT(n)  asm volatile("cp.async.wait_group %0;" :: "n"(n))
#define LDSM_X4(r0,r1,r2,r3,addr) \
    asm volatile("ldmatrix.sync.aligned.m8n8.x4.shared.b16 {%0,%1,%2,%3}, [%4];" \
        : "=r"(r0),"=r"(r1),"=r"(r2),"=r"(r3) : "r"(addr))
#define LDSM_X4_T(r0,r1,r2,r3,addr) \
    asm volatile("ldmatrix.sync.aligned.m8n8.x4.trans.shared.b16 {%0,%1,%2,%3}, [%4];" \
        : "=r"(r0),"=r"(r1),"=r"(r2),"=r"(r3) : "r"(addr))
#define MMAH(c, a, b) \
    asm volatile("mma.sync.aligned.m16n8k16.row.col.f32.f16.f16.f32 " \
        "{%0,%1,%2,%3}, {%4,%5,%6,%7}, {%8,%9}, {%0,%1,%2,%3};" \
        : "+f"((c)[0]),"+f"((c)[1]),"+f"((c)[2]),"+f"((c)[3]) \
        : "r"((a)[0]),"r"((a)[1]),"r"((a)[2]),"r"((a)[3]), "r"((b)[0]),"r"((b)[1]))

__device__ __forceinline__ uint32_t pk_h2(float a, float b) {
    __half2 h = __floats2half2_rn(a, b);
    return *(uint32_t*)&h;
}

// ---------------- prep kernels ----------------
// activations: single fp16 word
__global__ void xhalf_kernel(const float* __restrict__ src, __half* __restrict__ dst) {
    int i = blockIdx.x * 256 + threadIdx.x;
    float4 v = ((const float4*)src)[i];
    __half2 a = __floats2half2_rn(v.x, v.y);
    __half2 b = __floats2half2_rn(v.z, v.w);
    ((uint2*)dst)[i] = make_uint2(*(uint32_t*)&a, *(uint32_t*)&b);
}
// weights: scale x256, split hi/lo fp16
__global__ void wsplit_kernel(const float* __restrict__ src, __half* __restrict__ hi,
                              __half* __restrict__ lo) {
    int i = blockIdx.x * 256 + threadIdx.x;
    float x = src[i] * WSCL;
    __half h = __float2half_rn(x);
    hi[i] = h;
    lo[i] = __float2half_rn(x - __half2float(h));
}

// ---------------- fp16 x2 GEMM core, cp.async 2-stage, BK=32 ----------------
// smem/stage: 3 tensors (Ah, Wh, Wl) x 128 rows x 80B = 30720 B
#define LDA 40
#define GF_TEN 10240
#define GF_STG 30720

__device__ __forceinline__ void gemm_core_h(
    uint32_t sbase,
    const __half* __restrict__ Ah,
    const __half* __restrict__ Wh, const __half* __restrict__ Wl,
    int m0, int n0, float acc[4][4][4])
{
    const int tid = threadIdx.x, wid = tid >> 5, lane = tid & 31;
    const int wm0 = (wid & 1) * 64, wn0 = (wid >> 1) * 32;
    const int a_row = wm0 + (lane & 15);
    const int b_row = wn0 + (lane & 7) + ((lane >> 4) << 3);
    const int a_coff = (lane >> 4) * 8;
    const int b_coff = ((lane >> 3) & 1) * 8;
    const int lr = tid >> 2;
    const int lc = (tid & 3) * 8;

#define GH_LOAD(st, k0) do { \
        const uint32_t sb_ = sbase + (st) * GF_STG; \
        _Pragma("unroll") \
        for (int i_ = 0; i_ < 2; i_++) { \
            const int r_ = i_ * 64 + lr; \
            const uint32_t off_ = (uint32_t)((r_ * LDA + lc) * 2); \
            const size_t ga_ = (size_t)(m0 + r_) * Hdim + (k0) + lc; \
            const size_t gb_ = (size_t)(n0 + r_) * Hdim + (k0) + lc; \
            cp16(sb_ + off_,              Ah + ga_); \
            cp16(sb_ + GF_TEN + off_,     Wh + gb_); \
            cp16(sb_ + 2 * GF_TEN + off_, Wl + gb_); \
        } } while (0)

    GH_LOAD(0, 0);
    CP_COMMIT();

    for (int it = 0; it < 32; it++) {
        if (it < 31) {
            GH_LOAD((it + 1) & 1, (it + 1) * 32);
            CP_COMMIT();
            CP_WAIT(1);
        } else {
            CP_WAIT(0);
        }
        __syncthreads();

        const uint32_t sb = sbase + (it & 1) * GF_STG;
        const uint32_t aA = sb, aWh = sb + GF_TEN, aWl = sb + 2 * GF_TEN;

#pragma unroll
        for (int kf = 0; kf < 2; kf++) {
            const int kk = kf * 16;
            uint32_t ah[4][4];
#pragma unroll
            for (int mf = 0; mf < 4; mf++) {
                const uint32_t off = (uint32_t)(((a_row + mf * 16) * LDA + kk + a_coff) * 2);
                LDSM_X4(ah[mf][0], ah[mf][1], ah[mf][2], ah[mf][3], aA + off);
            }
#pragma unroll
            for (int nfp = 0; nfp < 2; nfp++) {
                const uint32_t off = (uint32_t)(((b_row + nfp * 16) * LDA + kk + b_coff) * 2);
                uint32_t wh[4], wl[4];
                LDSM_X4(wh[0], wh[1], wh[2], wh[3], aWh + off);
                LDSM_X4(wl[0], wl[1], wl[2], wl[3], aWl + off);
#pragma unroll
                for (int mf = 0; mf < 4; mf++) {
#pragma unroll
                    for (int hf = 0; hf < 2; hf++) {
                        float* c = acc[mf][nfp * 2 + hf];
                        MMAH(c, ah[mf], wh + hf * 2);
                        MMAH(c, ah[mf], wl + hf * 2);
                    }
                }
            }
        }
        __syncthreads();
    }
#undef GH_LOAD
}

// ---- fused QKV projection: Q -> hi only; K,V -> hi/lo fp16 head layout ----
__global__ void __launch_bounds__(256) gemm_qkv(
    const __half* __restrict__ Ah,
    const __half* __restrict__ Wh, const __half* __restrict__ Wl,
    const float* __restrict__ bq, const float* __restrict__ bk, const float* __restrict__ bv,
    __half* __restrict__ qh,
    __half* __restrict__ kh, __half* __restrict__ kl,
    __half* __restrict__ vh, __half* __restrict__ vl)
{
    extern __shared__ char dsm[];
    const uint32_t sbase = smem_u32(dsm);
    const int tid = threadIdx.x, wid = tid >> 5, lane = tid & 31;
    const int n0 = blockIdx.x * 128, m0 = blockIdx.y * 128;

    float acc[4][4][4];
#pragma unroll
    for (int i = 0; i < 4; i++)
#pragma unroll
        for (int j = 0; j < 4; j++)
#pragma unroll
            for (int v = 0; v < 4; v++) acc[i][j][v] = 0.f;

    gemm_core_h(sbase, Ah, Wh, Wl, m0, n0, acc);

    const int proj = n0 >> 10;
    const float* bias = (proj == 0) ? bq : (proj == 1) ? bk : bv;
    __half* outH = (proj == 0) ? qh : (proj == 1) ? kh : vh;
    __half* outL = (proj == 1) ? kl : vl;   // unused for proj 0

    const int wm0 = (wid & 1) * 64, wn0 = (wid >> 1) * 32;
    const int rbase = m0 + wm0 + (lane >> 2);
    const int cbase = n0 + wn0 + (lane & 3) * 2;
#pragma unroll
    for (int mf = 0; mf < 4; mf++) {
#pragma unroll
        for (int nf = 0; nf < 4; nf++) {
#pragma unroll
            for (int half = 0; half < 2; half++) {
                const int r = rbase + mf * 16 + half * 8;
                const int c = cbase + nf * 8;
                const int np = c & 1023;
                float v0 = fmaf(acc[mf][nf][half*2+0], WDSC, bias[np]);
                float v1 = fmaf(acc[mf][nf][half*2+1], WDSC, bias[np+1]);
                const int b = r >> 11, s = r & (Slen - 1);
                const int h = np >> 6, d = np & 63;
                const size_t idx = (((size_t)(b * NHn + h) * Slen) + s) * HDn + d;
                __half h0 = __float2half_rn(v0);
                __half h1 = __float2half_rn(v1);
                __half2 hv; hv.x = h0; hv.y = h1;
                *(uint32_t*)(outH + idx) = *(uint32_t*)&hv;
                if (proj != 0) {
                    *(uint32_t*)(outL + idx) = pk_h2(v0 - __half2float(h0),
                                                     v1 - __half2float(h1));
                }
            }
        }
    }
}

// ---- output projection: fp32 out + bias + residual ----
__global__ void __launch_bounds__(256) gemm_out(
    const __half* __restrict__ Ah,
    const __half* __restrict__ Wh, const __half* __restrict__ Wl,
    const float* __restrict__ bias, const float* __restrict__ res, float* __restrict__ out)
{
    extern __shared__ char dsm[];
    const uint32_t sbase = smem_u32(dsm);
    const int tid = threadIdx.x, wid = tid >> 5, lane = tid & 31;
    const int n0 = blockIdx.x * 128, m0 = blockIdx.y * 128;

    float acc[4][4][4];
#pragma unroll
    for (int i = 0; i < 4; i++)
#pragma unroll
        for (int j = 0; j < 4; j++)
#pragma unroll
            for (int v = 0; v < 4; v++) acc[i][j][v] = 0.f;

    gemm_core_h(sbase, Ah, Wh, Wl, m0, n0, acc);

    const int wm0 = (wid & 1) * 64, wn0 = (wid >> 1) * 32;
    const int rbase = m0 + wm0 + (lane >> 2);
    const int cbase = n0 + wn0 + (lane & 3) * 2;
#pragma unroll
    for (int mf = 0; mf < 4; mf++) {
#pragma unroll
        for (int nf = 0; nf < 4; nf++) {
#pragma unroll
            for (int half = 0; half < 2; half++) {
                const int r = rbase + mf * 16 + half * 8;
                const int c = cbase + nf * 8;
                const size_t idx = (size_t)r * Hdim + c;
                float2 rv = *(const float2*)(res + idx);
                float2 o;
                o.x = fmaf(acc[mf][nf][half*2+0], WDSC, bias[c] + rv.x);
                o.y = fmaf(acc[mf][nf][half*2+1], WDSC, bias[c+1] + rv.y);
                *(float2*)(out + idx) = o;
            }
        }
    }
}

// ---------------- fp16 x2 flash attention, causal, cp.async 2-stage K/V ----------------
// smem/stage: 4 tensors (kh,kl,vh,vl) x 64 x 144B = 36864 B; Q hi staged in stage0 front.
#define ALD 72
#define A_TEN 9216
#define A_STG 36864
__global__ void __launch_bounds__(128) attn_mma(
    const __half* __restrict__ Qh,
    const __half* __restrict__ Kh, const __half* __restrict__ Kl,
    const __half* __restrict__ Vh, const __half* __restrict__ Vl,
    __half* __restrict__ Ch)
{
    extern __shared__ char dsm[];
    const uint32_t sbase = smem_u32(dsm);
    const int tid = threadIdx.x, wid = tid >> 5, lane = tid & 31;
    const int qt = blockIdx.x, h = blockIdx.y, b = blockIdx.z;
    const int m0 = qt * 64, wq0 = wid * 16;
    const size_t base = (size_t)(b * NHn + h) * Slen * HDn;

    // ---- stage Q hi into stage0 front ----
    {
        const __half* srcH = Qh + base + (size_t)m0 * HDn;
#pragma unroll
        for (int i = 0; i < 4; i++) {
            int u = i * 128 + tid, r = u >> 3, c = u & 7;
            int cs = c ^ ((r & 3) << 1);
            *(uint4*)(dsm + (r * ALD + cs * 8) * 2) = *(const uint4*)(srcH + r * 64 + c * 8);
        }
    }
    __syncthreads();

    const int rA = (lane & 7) + ((lane >> 3) & 1) * 8;
    const int cA = (lane >> 4) & 1;
    const int rB = (lane & 7) + ((lane >> 4) << 3);
    const int cB = (lane >> 3) & 1;
    const int swzA = (rA & 3) << 1;
    const int swzB = (rB & 3) << 1;

    uint32_t qfh[4][4];
    {
        const int row = wq0 + rA;
        const uint32_t rb = (uint32_t)(row * (ALD * 2));
        const int swz = (row & 3) << 1;
#pragma unroll
        for (int kb = 0; kb < 4; kb++) {
            const uint32_t off = rb + (uint32_t)(((2 * kb + cA) ^ swz) * 16);
            LDSM_X4(qfh[kb][0], qfh[kb][1], qfh[kb][2], qfh[kb][3], sbase + off);
        }
    }
    __syncthreads();

#define A_LOAD(st, k0) do { \
        const uint32_t sb_ = sbase + (st) * A_STG; \
        const __half* k0p_ = Kh + base + (size_t)(k0) * HDn; \
        const __half* k1p_ = Kl + base + (size_t)(k0) * HDn; \
        const __half* v0p_ = Vh + base + (size_t)(k0) * HDn; \
        const __half* v1p_ = Vl + base + (size_t)(k0) * HDn; \
        _Pragma("unroll") \
        for (int i_ = 0; i_ < 4; i_++) { \
            int u_ = i_ * 128 + tid, r_ = u_ >> 3, c_ = u_ & 7; \
            int cs_ = c_ ^ ((r_ & 3) << 1); \
            uint32_t so_ = (uint32_t)((r_ * ALD + cs_ * 8) * 2); \
            int go_ = r_ * 64 + c_ * 8; \
            cp16(sb_ + so_,             k0p_ + go_); \
            cp16(sb_ + A_TEN + so_,     k1p_ + go_); \
            cp16(sb_ + 2 * A_TEN + so_, v0p_ + go_); \
            cp16(sb_ + 3 * A_TEN + so_, v1p_ + go_); \
        } } while (0)

    A_LOAD(0, 0);
    CP_COMMIT();

    float o[8][4];
#pragma unroll
    for (int i = 0; i < 8; i++)
#pragma unroll
        for (int v = 0; v < 4; v++) o[i][v] = 0.f;
    float mr0 = -1e30f, mr1 = -1e30f, lr0 = 0.f, lr1 = 0.f;

    for (int kt = 0; kt <= qt; kt++) {
        if (kt < qt) {
            A_LOAD((kt + 1) & 1, (kt + 1) * 64);
            CP_COMMIT();
            CP_WAIT(1);
        } else {
            CP_WAIT(0);
        }
        __syncthreads();

        const uint32_t sb = sbase + (kt & 1) * A_STG;
        const uint32_t aKh = sb, aKl = sb + A_TEN;
        const uint32_t aVh = sb + 2 * A_TEN, aVl = sb + 3 * A_TEN;

        // ---- S = Q K^T (fp16 x2 on K side) ----
        float s[8][4];
#pragma unroll
        for (int i = 0; i < 8; i++)
#pragma unroll
            for (int v = 0; v < 4; v++) s[i][v] = 0.f;
#pragma unroll
        for (int kb = 0; kb < 4; kb++) {
#pragma unroll
            for (int np = 0; np < 4; np++) {
                const int row = np * 16 + rB;
                const uint32_t off = (uint32_t)(row * (ALD * 2) + (((2 * kb + cB) ^ swzB)) * 16);
                uint32_t kh[4], kl[4];
                LDSM_X4(kh[0], kh[1], kh[2], kh[3], aKh + off);
                LDSM_X4(kl[0], kl[1], kl[2], kl[3], aKl + off);
                MMAH(s[2*np],   qfh[kb], kh);     MMAH(s[2*np],   qfh[kb], kl);
                MMAH(s[2*np+1], qfh[kb], kh + 2); MMAH(s[2*np+1], qfh[kb], kl + 2);
            }
        }

#pragma unroll
        for (int nf = 0; nf < 8; nf++)
#pragma unroll
            for (int v = 0; v < 4; v++) s[nf][v] *= 0.125f;
        if (kt == qt) {
            const int row0 = wq0 + (lane >> 2), row1 = row0 + 8;
            const int colb = (lane & 3) * 2;
#pragma unroll
            for (int nf = 0; nf < 8; nf++) {
                const int c0 = nf * 8 + colb, c1 = c0 + 1;
                if (c0 > row0) s[nf][0] = -1e30f;
                if (c1 > row0) s[nf][1] = -1e30f;
                if (c0 > row1) s[nf][2] = -1e30f;
                if (c1 > row1) s[nf][3] = -1e30f;
            }
        }

        // ---- online softmax ----
        float mx0 = s[0][0], mx1 = s[0][2];
#pragma unroll
        for (int nf = 0; nf < 8; nf++) {
            mx0 = fmaxf(mx0, fmaxf(s[nf][0], s[nf][1]));
            mx1 = fmaxf(mx1, fmaxf(s[nf][2], s[nf][3]));
        }
        mx0 = fmaxf(mx0, __shfl_xor_sync(0xffffffffu, mx0, 1));
        mx0 = fmaxf(mx0, __shfl_xor_sync(0xffffffffu, mx0, 2));
        mx1 = fmaxf(mx1, __shfl_xor_sync(0xffffffffu, mx1, 1));
        mx1 = fmaxf(mx1, __shfl_xor_sync(0xffffffffu, mx1, 2));
        const float nm0 = fmaxf(mr0, mx0), nm1 = fmaxf(mr1, mx1);
        const float cr0 = __expf(mr0 - nm0), cr1 = __expf(mr1 - nm1);
        lr0 *= cr0; lr1 *= cr1;
#pragma unroll
        for (int nf = 0; nf < 8; nf++) {
            o[nf][0] *= cr0; o[nf][1] *= cr0;
            o[nf][2] *= cr1; o[nf][3] *= cr1;
        }
        mr0 = nm0; mr1 = nm1;

        uint32_t ph[8], phb[8];
#pragma unroll
        for (int nf = 0; nf < 8; nf++) {
            float p0 = __expf(s[nf][0] - nm0), p1 = __expf(s[nf][1] - nm0);
            float p2 = __expf(s[nf][2] - nm1), p3 = __expf(s[nf][3] - nm1);
            lr0 += p0 + p1; lr1 += p2 + p3;
            ph[nf]  = pk_h2(p0, p1);
            phb[nf] = pk_h2(p2, p3);
        }

        // ---- O += P V (fp16 x2 on V side) ----
#pragma unroll
        for (int kb = 0; kb < 4; kb++) {
            uint32_t pah[4] = { ph[2*kb], phb[2*kb], ph[2*kb+1], phb[2*kb+1] };
            const int row = kb * 16 + rA;
            const uint32_t rb = (uint32_t)(row * (ALD * 2));
#pragma unroll
            for (int np = 0; np < 4; np++) {
                const uint32_t off = rb + (uint32_t)(((2 * np + cA) ^ swzA) * 16);
                uint32_t vh[4], vl[4];
                LDSM_X4_T(vh[0], vh[1], vh[2], vh[3], aVh + off);
                LDSM_X4_T(vl[0], vl[1], vl[2], vl[3], aVl + off);
                MMAH(o[2*np],   pah, vh);     MMAH(o[2*np],   pah, vl);
                MMAH(o[2*np+1], pah, vh + 2); MMAH(o[2*np+1], pah, vl + 2);
            }
        }
        __syncthreads();
    }
#undef A_LOAD

    lr0 += __shfl_xor_sync(0xffffffffu, lr0, 1);
    lr0 += __shfl_xor_sync(0xffffffffu, lr0, 2);
    lr1 += __shfl_xor_sync(0xffffffffu, lr1, 1);
    lr1 += __shfl_xor_sync(0xffffffffu, lr1, 2);
    const float iv0 = 1.f / lr0, iv1 = 1.f / lr1;

    const int s0 = m0 + wq0 + (lane >> 2), s1 = s0 + 8;
    const size_t rb0 = (size_t)(b * Slen + s0) * Hdim + h * 64;
    const size_t rb1 = (size_t)(b * Slen + s1) * Hdim + h * 64;
#pragma unroll
    for (int nf = 0; nf < 8; nf++) {
        const int col = nf * 8 + (lane & 3) * 2;
        *(uint32_t*)(Ch + rb0 + col) = pk_h2(o[nf][0] * iv0, o[nf][1] * iv0);
        *(uint32_t*)(Ch + rb1 + col) = pk_h2(o[nf][2] * iv1, o[nf][3] * iv1);
    }
}

// ---------------- LayerNorm ----------------
__global__ void ln_kernel(const float* __restrict__ y, const float* __restrict__ g,
                          const float* __restrict__ be, float* __restrict__ out)
{
    __shared__ float red[256];
    const int row = blockIdx.x, tid = threadIdx.x;
    const float4 v = ((const float4*)(y + (size_t)row * Hdim))[tid];
    float sum = v.x + v.y + v.z + v.w;
    red[tid] = sum; __syncthreads();
    for (int s = 128; s > 0; s >>= 1) { if (tid < s) red[tid] += red[tid + s]; __syncthreads(); }
    const float mu = red[0] * (1.f / 1024.f);
    __syncthreads();
    const float d0 = v.x - mu, d1 = v.y - mu, d2 = v.z - mu, d3 = v.w - mu;
    red[tid] = d0 * d0 + d1 * d1 + d2 * d2 + d3 * d3; __syncthreads();
    for (int s = 128; s > 0; s >>= 1) { if (tid < s) red[tid] += red[tid + s]; __syncthreads(); }
    const float inv = rsqrtf(red[0] * (1.f / 1024.f) + EPSf);
    const float4 gg = ((const float4*)g)[tid];
    const float4 bb = ((const float4*)be)[tid];
    float4 o;
    o.x = d0 * inv * gg.x + bb.x;
    o.y = d1 * inv * gg.y + bb.y;
    o.z = d2 * inv * gg.z + bb.z;
    o.w = d3 * inv * gg.w + bb.w;
    ((float4*)(out + (size_t)row * Hdim))[tid] = o;
}

// ---------------- launch ----------------
extern "C" void kernel_launch(void* const* d_in, const int* in_sizes, int n_in,
                              void* d_out, int out_size)
{
    const float* x    = (const float*)d_in[0];
    const float* Wq   = (const float*)d_in[1];
    const float* bq   = (const float*)d_in[2];
    const float* Wk   = (const float*)d_in[3];
    const float* bk   = (const float*)d_in[4];
    const float* Wv   = (const float*)d_in[5];
    const float* bv   = (const float*)d_in[6];
    const float* Wo   = (const float*)d_in[7];
    const float* bo   = (const float*)d_in[8];
    const float* ln_g = (const float*)d_in[9];
    const float* ln_b = (const float*)d_in[10];
    float* out = (float*)d_out;

    float* yp;
    __half *xh, *wh, *wl, *qh, *kh, *kl, *vh, *vl, *ch;
    cudaGetSymbolAddress((void**)&yp, g_y);
    cudaGetSymbolAddress((void**)&xh, g_xh);
    cudaGetSymbolAddress((void**)&wh, g_wh);
    cudaGetSymbolAddress((void**)&wl, g_wl);
    cudaGetSymbolAddress((void**)&qh, g_qh);
    cudaGetSymbolAddress((void**)&kh, g_kh);
    cudaGetSymbolAddress((void**)&kl, g_kl);
    cudaGetSymbolAddress((void**)&vh, g_vh);
    cudaGetSymbolAddress((void**)&vl, g_vl);
    cudaGetSymbolAddress((void**)&ch, g_ch);

    static bool attr_done = false;
    if (!attr_done) {
        cudaFuncSetAttribute(gemm_qkv, cudaFuncAttributeMaxDynamicSharedMemorySize, 2 * GF_STG);
        cudaFuncSetAttribute(gemm_out, cudaFuncAttributeMaxDynamicSharedMemorySize, 2 * GF_STG);
        cudaFuncSetAttribute(attn_mma, cudaFuncAttributeMaxDynamicSharedMemorySize, 2 * A_STG);
        attr_done = true;
    }

    const int WSZ = Hdim * Hdim;
    xhalf_kernel<<<Mtot * Hdim / 1024, 256>>>(x, xh);
    wsplit_kernel<<<WSZ / 256, 256>>>(Wq, wh + 0 * WSZ, wl + 0 * WSZ);
    wsplit_kernel<<<WSZ / 256, 256>>>(Wk, wh + 1 * WSZ, wl + 1 * WSZ);
    wsplit_kernel<<<WSZ / 256, 256>>>(Wv, wh + 2 * WSZ, wl + 2 * WSZ);
    wsplit_kernel<<<WSZ / 256, 256>>>(Wo, wh + 3 * WSZ, wl + 3 * WSZ);

    gemm_qkv<<<dim3(3 * Hdim / 128, Mtot / 128), 256, 2 * GF_STG>>>(
        xh, wh, wl, bq, bk, bv, qh, kh, kl, vh, vl);

    attn_mma<<<dim3(Slen / 64, NHn, Bsz), 128, 2 * A_STG>>>(qh, kh, kl, vh, vl, ch);

    gemm_out<<<dim3(Hdim / 128, Mtot / 128), 256, 2 * GF_STG>>>(
        ch, wh + 3 * WSZ, wl + 3 * WSZ, bo, x, yp);

    ln_kernel<<<Mtot, 256>>>(yp, ln_g, ln_b, out);
}

// round 11
// speedup vs baseline: 4.1718x; 1.5667x over previous
#include <cuda_runtime.h>
#include <cuda_fp16.h>
#include <stdint.h>
#include <math.h>

#define Bsz   2
#define Slen  2048
#define Hdim  1024
#define NHn   16
#define HDn   64
#define Mtot  (Bsz*Slen)
#define EPSf  1e-12f
#define WSCL  256.f
#define WDSC  (1.f/256.f)

// -------- scratch (no allocations allowed) --------
__device__ float g_y[Mtot*Hdim];
__device__ __half g_xh[Mtot*Hdim];
__device__ __half g_wh[4*Hdim*Hdim];
__device__ __half g_qh[Mtot*Hdim];
__device__ __half g_kh[Mtot*Hdim];
__device__ __half g_vh[Mtot*Hdim];
__device__ __half g_ch[Mtot*Hdim];

// ---------------- helpers ----------------
__device__ __forceinline__ uint32_t smem_u32(const void* p) {
    uint32_t a;
    asm("{ .reg .u64 t; cvta.to.shared.u64 t, %1; cvt.u32.u64 %0, t; }" : "=r"(a) : "l"(p));
    return a;
}
__device__ __forceinline__ void cp16(uint32_t dst, const void* src) {
    asm volatile("cp.async.cg.shared.global [%0], [%1], 16;" :: "r"(dst), "l"(src));
}
#define CP_COMMIT() asm volatile("cp.async.commit_group;")
#define CP_WAIT(n)  asm volatile("cp.async.wait_group %0;" :: "n"(n))
#define LDSM_X4(r0,r1,r2,r3,addr) \
    asm volatile("ldmatrix.sync.aligned.m8n8.x4.shared.b16 {%0,%1,%2,%3}, [%4];" \
        : "=r"(r0),"=r"(r1),"=r"(r2),"=r"(r3) : "r"(addr))
#define LDSM_X4_T(r0,r1,r2,r3,addr) \
    asm volatile("ldmatrix.sync.aligned.m8n8.x4.trans.shared.b16 {%0,%1,%2,%3}, [%4];" \
        : "=r"(r0),"=r"(r1),"=r"(r2),"=r"(r3) : "r"(addr))
#define MMAH(c, a, b) \
    asm volatile("mma.sync.aligned.m16n8k16.row.col.f32.f16.f16.f32 " \
        "{%0,%1,%2,%3}, {%4,%5,%6,%7}, {%8,%9}, {%0,%1,%2,%3};" \
        : "+f"((c)[0]),"+f"((c)[1]),"+f"((c)[2]),"+f"((c)[3]) \
        : "r"((a)[0]),"r"((a)[1]),"r"((a)[2]),"r"((a)[3]), "r"((b)[0]),"r"((b)[1]))

__device__ __forceinline__ uint32_t pk_h2(float a, float b) {
    __half2 h = __floats2half2_rn(a, b);
    return *(uint32_t*)&h;
}

// ---------------- prep kernels ----------------
__global__ void xhalf_kernel(const float* __restrict__ src, __half* __restrict__ dst) {
    int i = blockIdx.x * 256 + threadIdx.x;
    float4 v = ((const float4*)src)[i];
    __half2 a = __floats2half2_rn(v.x, v.y);
    __half2 b = __floats2half2_rn(v.z, v.w);
    ((uint2*)dst)[i] = make_uint2(*(uint32_t*)&a, *(uint32_t*)&b);
}
__global__ void whalf_kernel(const float* __restrict__ src, __half* __restrict__ dst) {
    int i = blockIdx.x * 256 + threadIdx.x;
    float4 v = ((const float4*)src)[i];
    __half2 a = __floats2half2_rn(v.x * WSCL, v.y * WSCL);
    __half2 b = __floats2half2_rn(v.z * WSCL, v.w * WSCL);
    ((uint2*)dst)[i] = make_uint2(*(uint32_t*)&a, *(uint32_t*)&b);
}

// ---------------- fp16 x1 GEMM core, cp.async 2-stage, BK=32 ----------------
// smem/stage: 2 tensors (Ah, Wh) x 128 rows x 80B = 20480 B
#define LDA 40
#define GF_TEN 10240
#define GF_STG 20480

__device__ __forceinline__ void gemm_core_h(
    uint32_t sbase,
    const __half* __restrict__ Ah, const __half* __restrict__ Wh,
    int m0, int n0, float acc[4][4][4])
{
    const int tid = threadIdx.x, wid = tid >> 5, lane = tid & 31;
    const int wm0 = (wid & 1) * 64, wn0 = (wid >> 1) * 32;
    const int a_row = wm0 + (lane & 15);
    const int b_row = wn0 + (lane & 7) + ((lane >> 4) << 3);
    const int a_coff = (lane >> 4) * 8;
    const int b_coff = ((lane >> 3) & 1) * 8;
    const int lr = tid >> 2;
    const int lc = (tid & 3) * 8;

#define GH_LOAD(st, k0) do { \
        const uint32_t sb_ = sbase + (st) * GF_STG; \
        _Pragma("unroll") \
        for (int i_ = 0; i_ < 2; i_++) { \
            const int r_ = i_ * 64 + lr; \
            const uint32_t off_ = (uint32_t)((r_ * LDA + lc) * 2); \
            cp16(sb_ + off_,          Ah + (size_t)(m0 + r_) * Hdim + (k0) + lc); \
            cp16(sb_ + GF_TEN + off_, Wh + (size_t)(n0 + r_) * Hdim + (k0) + lc); \
        } } while (0)

    GH_LOAD(0, 0);
    CP_COMMIT();

    for (int it = 0; it < 32; it++) {
        if (it < 31) {
            GH_LOAD((it + 1) & 1, (it + 1) * 32);
            CP_COMMIT();
            CP_WAIT(1);
        } else {
            CP_WAIT(0);
        }
        __syncthreads();

        const uint32_t sb = sbase + (it & 1) * GF_STG;
        const uint32_t aA = sb, aW = sb + GF_TEN;

#pragma unroll
        for (int kf = 0; kf < 2; kf++) {
            const int kk = kf * 16;
            uint32_t ah[4][4];
#pragma unroll
            for (int mf = 0; mf < 4; mf++) {
                const uint32_t off = (uint32_t)(((a_row + mf * 16) * LDA + kk + a_coff) * 2);
                LDSM_X4(ah[mf][0], ah[mf][1], ah[mf][2], ah[mf][3], aA + off);
            }
#pragma unroll
            for (int nfp = 0; nfp < 2; nfp++) {
                const uint32_t off = (uint32_t)(((b_row + nfp * 16) * LDA + kk + b_coff) * 2);
                uint32_t wh[4];
                LDSM_X4(wh[0], wh[1], wh[2], wh[3], aW + off);
#pragma unroll
                for (int mf = 0; mf < 4; mf++) {
#pragma unroll
                    for (int hf = 0; hf < 2; hf++)
                        MMAH(acc[mf][nfp * 2 + hf], ah[mf], wh + hf * 2);
                }
            }
        }
        __syncthreads();
    }
#undef GH_LOAD
}

// ---- fused QKV projection: fp16 head-layout outputs ----
__global__ void __launch_bounds__(256) gemm_qkv(
    const __half* __restrict__ Ah, const __half* __restrict__ Wh,
    const float* __restrict__ bq, const float* __restrict__ bk, const float* __restrict__ bv,
    __half* __restrict__ qh, __half* __restrict__ kh, __half* __restrict__ vh)
{
    extern __shared__ char dsm[];
    const uint32_t sbase = smem_u32(dsm);
    const int tid = threadIdx.x, wid = tid >> 5, lane = tid & 31;
    const int n0 = blockIdx.x * 128, m0 = blockIdx.y * 128;

    float acc[4][4][4];
#pragma unroll
    for (int i = 0; i < 4; i++)
#pragma unroll
        for (int j = 0; j < 4; j++)
#pragma unroll
            for (int v = 0; v < 4; v++) acc[i][j][v] = 0.f;

    gemm_core_h(sbase, Ah, Wh, m0, n0, acc);

    const int proj = n0 >> 10;
    const float* bias = (proj == 0) ? bq : (proj == 1) ? bk : bv;
    __half* outH = (proj == 0) ? qh : (proj == 1) ? kh : vh;

    const int wm0 = (wid & 1) * 64, wn0 = (wid >> 1) * 32;
    const int rbase = m0 + wm0 + (lane >> 2);
    const int cbase = n0 + wn0 + (lane & 3) * 2;
#pragma unroll
    for (int mf = 0; mf < 4; mf++) {
#pragma unroll
        for (int nf = 0; nf < 4; nf++) {
#pragma unroll
            for (int half = 0; half < 2; half++) {
                const int r = rbase + mf * 16 + half * 8;
                const int c = cbase + nf * 8;
                const int np = c & 1023;
                float v0 = fmaf(acc[mf][nf][half*2+0], WDSC, bias[np]);
                float v1 = fmaf(acc[mf][nf][half*2+1], WDSC, bias[np+1]);
                const int b = r >> 11, s = r & (Slen - 1);
                const int h = np >> 6, d = np & 63;
                const size_t idx = (((size_t)(b * NHn + h) * Slen) + s) * HDn + d;
                *(uint32_t*)(outH + idx) = pk_h2(v0, v1);
            }
        }
    }
}

// ---- output projection: fp32 out + bias + residual ----
__global__ void __launch_bounds__(256) gemm_out(
    const __half* __restrict__ Ah, const __half* __restrict__ Wh,
    const float* __restrict__ bias, const float* __restrict__ res, float* __restrict__ out)
{
    extern __shared__ char dsm[];
    const uint32_t sbase = smem_u32(dsm);
    const int tid = threadIdx.x, wid = tid >> 5, lane = tid & 31;
    const int n0 = blockIdx.x * 128, m0 = blockIdx.y * 128;

    float acc[4][4][4];
#pragma unroll
    for (int i = 0; i < 4; i++)
#pragma unroll
        for (int j = 0; j < 4; j++)
#pragma unroll
            for (int v = 0; v < 4; v++) acc[i][j][v] = 0.f;

    gemm_core_h(sbase, Ah, Wh, m0, n0, acc);

    const int wm0 = (wid & 1) * 64, wn0 = (wid >> 1) * 32;
    const int rbase = m0 + wm0 + (lane >> 2);
    const int cbase = n0 + wn0 + (lane & 3) * 2;
#pragma unroll
    for (int mf = 0; mf < 4; mf++) {
#pragma unroll
        for (int nf = 0; nf < 4; nf++) {
#pragma unroll
            for (int half = 0; half < 2; half++) {
                const int r = rbase + mf * 16 + half * 8;
                const int c = cbase + nf * 8;
                const size_t idx = (size_t)r * Hdim + c;
                float2 rv = *(const float2*)(res + idx);
                float2 o;
                o.x = fmaf(acc[mf][nf][half*2+0], WDSC, bias[c] + rv.x);
                o.y = fmaf(acc[mf][nf][half*2+1], WDSC, bias[c+1] + rv.y);
                *(float2*)(out + idx) = o;
            }
        }
    }
}

// ---------------- fp16 x1 flash attention, causal, cp.async 2-stage K/V ----------------
// smem/stage: 2 tensors (kh, vh) x 64 x 144B = 18432 B; Q staged in stage0 front.
#define ALD 72
#define A_TEN 9216
#define A_STG 18432
__global__ void __launch_bounds__(128) attn_mma(
    const __half* __restrict__ Qh, const __half* __restrict__ Kh,
    const __half* __restrict__ Vh, __half* __restrict__ Ch)
{
    extern __shared__ char dsm[];
    const uint32_t sbase = smem_u32(dsm);
    const int tid = threadIdx.x, wid = tid >> 5, lane = tid & 31;
    const int qt = blockIdx.x, h = blockIdx.y, b = blockIdx.z;
    const int m0 = qt * 64, wq0 = wid * 16;
    const size_t base = (size_t)(b * NHn + h) * Slen * HDn;

    // ---- stage Q into stage0 front ----
    {
        const __half* srcH = Qh + base + (size_t)m0 * HDn;
#pragma unroll
        for (int i = 0; i < 4; i++) {
            int u = i * 128 + tid, r = u >> 3, c = u & 7;
            int cs = c ^ ((r & 3) << 1);
            *(uint4*)(dsm + (r * ALD + cs * 8) * 2) = *(const uint4*)(srcH + r * 64 + c * 8);
        }
    }
    __syncthreads();

    const int rA = (lane & 7) + ((lane >> 3) & 1) * 8;
    const int cA = (lane >> 4) & 1;
    const int rB = (lane & 7) + ((lane >> 4) << 3);
    const int cB = (lane >> 3) & 1;
    const int swzA = (rA & 3) << 1;
    const int swzB = (rB & 3) << 1;

    uint32_t qfh[4][4];
    {
        const int row = wq0 + rA;
        const uint32_t rb = (uint32_t)(row * (ALD * 2));
        const int swz = (row & 3) << 1;
#pragma unroll
        for (int kb = 0; kb < 4; kb++) {
            const uint32_t off = rb + (uint32_t)(((2 * kb + cA) ^ swz) * 16);
            LDSM_X4(qfh[kb][0], qfh[kb][1], qfh[kb][2], qfh[kb][3], sbase + off);
        }
    }
    __syncthreads();

#define A_LOAD(st, k0) do { \
        const uint32_t sb_ = sbase + (st) * A_STG; \
        const __half* kp_ = Kh + base + (size_t)(k0) * HDn; \
        const __half* vp_ = Vh + base + (size_t)(k0) * HDn; \
        _Pragma("unroll") \
        for (int i_ = 0; i_ < 4; i_++) { \
            int u_ = i_ * 128 + tid, r_ = u_ >> 3, c_ = u_ & 7; \
            int cs_ = c_ ^ ((r_ & 3) << 1); \
            uint32_t so_ = (uint32_t)((r_ * ALD + cs_ * 8) * 2); \
            int go_ = r_ * 64 + c_ * 8; \
            cp16(sb_ + so_,         kp_ + go_); \
            cp16(sb_ + A_TEN + so_, vp_ + go_); \
        } } while (0)

    A_LOAD(0, 0);
    CP_COMMIT();

    float o[8][4];
#pragma unroll
    for (int i = 0; i < 8; i++)
#pragma unroll
        for (int v = 0; v < 4; v++) o[i][v] = 0.f;
    float mr0 = -1e30f, mr1 = -1e30f, lr0 = 0.f, lr1 = 0.f;

    for (int kt = 0; kt <= qt; kt++) {
        if (kt < qt) {
            A_LOAD((kt + 1) & 1, (kt + 1) * 64);
            CP_COMMIT();
            CP_WAIT(1);
        } else {
            CP_WAIT(0);
        }
        __syncthreads();

        const uint32_t sb = sbase + (kt & 1) * A_STG;
        const uint32_t aKh = sb, aVh = sb + A_TEN;

        // ---- S = Q K^T ----
        float s[8][4];
#pragma unroll
        for (int i = 0; i < 8; i++)
#pragma unroll
            for (int v = 0; v < 4; v++) s[i][v] = 0.f;
#pragma unroll
        for (int kb = 0; kb < 4; kb++) {
#pragma unroll
            for (int np = 0; np < 4; np++) {
                const int row = np * 16 + rB;
                const uint32_t off = (uint32_t)(row * (ALD * 2) + (((2 * kb + cB) ^ swzB)) * 16);
                uint32_t kh[4];
                LDSM_X4(kh[0], kh[1], kh[2], kh[3], aKh + off);
                MMAH(s[2*np],   qfh[kb], kh);
                MMAH(s[2*np+1], qfh[kb], kh + 2);
            }
        }

#pragma unroll
        for (int nf = 0; nf < 8; nf++)
#pragma unroll
            for (int v = 0; v < 4; v++) s[nf][v] *= 0.125f;
        if (kt == qt) {
            const int row0 = wq0 + (lane >> 2), row1 = row0 + 8;
            const int colb = (lane & 3) * 2;
#pragma unroll
            for (int nf = 0; nf < 8; nf++) {
                const int c0 = nf * 8 + colb, c1 = c0 + 1;
                if (c0 > row0) s[nf][0] = -1e30f;
                if (c1 > row0) s[nf][1] = -1e30f;
                if (c0 > row1) s[nf][2] = -1e30f;
                if (c1 > row1) s[nf][3] = -1e30f;
            }
        }

        // ---- online softmax ----
        float mx0 = s[0][0], mx1 = s[0][2];
#pragma unroll
        for (int nf = 0; nf < 8; nf++) {
            mx0 = fmaxf(mx0, fmaxf(s[nf][0], s[nf][1]));
            mx1 = fmaxf(mx1, fmaxf(s[nf][2], s[nf][3]));
        }
        mx0 = fmaxf(mx0, __shfl_xor_sync(0xffffffffu, mx0, 1));
        mx0 = fmaxf(mx0, __shfl_xor_sync(0xffffffffu, mx0, 2));
        mx1 = fmaxf(mx1, __shfl_xor_sync(0xffffffffu, mx1, 1));
        mx1 = fmaxf(mx1, __shfl_xor_sync(0xffffffffu, mx1, 2));
        const float nm0 = fmaxf(mr0, mx0), nm1 = fmaxf(mr1, mx1);
        const float cr0 = __expf(mr0 - nm0), cr1 = __expf(mr1 - nm1);
        lr0 *= cr0; lr1 *= cr1;
#pragma unroll
        for (int nf = 0; nf < 8; nf++) {
            o[nf][0] *= cr0; o[nf][1] *= cr0;
            o[nf][2] *= cr1; o[nf][3] *= cr1;
        }
        mr0 = nm0; mr1 = nm1;

        uint32_t ph[8], phb[8];
#pragma unroll
        for (int nf = 0; nf < 8; nf++) {
            float p0 = __expf(s[nf][0] - nm0), p1 = __expf(s[nf][1] - nm0);
            float p2 = __expf(s[nf][2] - nm1), p3 = __expf(s[nf][3] - nm1);
            lr0 += p0 + p1; lr1 += p2 + p3;
            ph[nf]  = pk_h2(p0, p1);
            phb[nf] = pk_h2(p2, p3);
        }

        // ---- O += P V ----
#pragma unroll
        for (int kb = 0; kb < 4; kb++) {
            uint32_t pah[4] = { ph[2*kb], phb[2*kb], ph[2*kb+1], phb[2*kb+1] };
            const int row = kb * 16 + rA;
            const uint32_t rb = (uint32_t)(row * (ALD * 2));
#pragma unroll
            for (int np = 0; np < 4; np++) {
                const uint32_t off = rb + (uint32_t)(((2 * np + cA) ^ swzA) * 16);
                uint32_t vh[4];
                LDSM_X4_T(vh[0], vh[1], vh[2], vh[3], aVh + off);
                MMAH(o[2*np],   pah, vh);
                MMAH(o[2*np+1], pah, vh + 2);
            }
        }
        __syncthreads();
    }
#undef A_LOAD

    lr0 += __shfl_xor_sync(0xffffffffu, lr0, 1);
    lr0 += __shfl_xor_sync(0xffffffffu, lr0, 2);
    lr1 += __shfl_xor_sync(0xffffffffu, lr1, 1);
    lr1 += __shfl_xor_sync(0xffffffffu, lr1, 2);
    const float iv0 = 1.f / lr0, iv1 = 1.f / lr1;

    const int s0 = m0 + wq0 + (lane >> 2), s1 = s0 + 8;
    const size_t rb0 = (size_t)(b * Slen + s0) * Hdim + h * 64;
    const size_t rb1 = (size_t)(b * Slen + s1) * Hdim + h * 64;
#pragma unroll
    for (int nf = 0; nf < 8; nf++) {
        const int col = nf * 8 + (lane & 3) * 2;
        *(uint32_t*)(Ch + rb0 + col) = pk_h2(o[nf][0] * iv0, o[nf][1] * iv0);
        *(uint32_t*)(Ch + rb1 + col) = pk_h2(o[nf][2] * iv1, o[nf][3] * iv1);
    }
}

// ---------------- LayerNorm ----------------
__global__ void ln_kernel(const float* __restrict__ y, const float* __restrict__ g,
                          const float* __restrict__ be, float* __restrict__ out)
{
    __shared__ float red[256];
    const int row = blockIdx.x, tid = threadIdx.x;
    const float4 v = ((const float4*)(y + (size_t)row * Hdim))[tid];
    float sum = v.x + v.y + v.z + v.w;
    red[tid] = sum; __syncthreads();
    for (int s = 128; s > 0; s >>= 1) { if (tid < s) red[tid] += red[tid + s]; __syncthreads(); }
    const float mu = red[0] * (1.f / 1024.f);
    __syncthreads();
    const float d0 = v.x - mu, d1 = v.y - mu, d2 = v.z - mu, d3 = v.w - mu;
    red[tid] = d0 * d0 + d1 * d1 + d2 * d2 + d3 * d3; __syncthreads();
    for (int s = 128; s > 0; s >>= 1) { if (tid < s) red[tid] += red[tid + s]; __syncthreads(); }
    const float inv = rsqrtf(red[0] * (1.f / 1024.f) + EPSf);
    const float4 gg = ((const float4*)g)[tid];
    const float4 bb = ((const float4*)be)[tid];
    float4 o;
    o.x = d0 * inv * gg.x + bb.x;
    o.y = d1 * inv * gg.y + bb.y;
    o.z = d2 * inv * gg.z + bb.z;
    o.w = d3 * inv * gg.w + bb.w;
    ((float4*)(out + (size_t)row * Hdim))[tid] = o;
}

// ---------------- launch ----------------
extern "C" void kernel_launch(void* const* d_in, const int* in_sizes, int n_in,
                              void* d_out, int out_size)
{
    const float* x    = (const float*)d_in[0];
    const float* Wq   = (const float*)d_in[1];
    const float* bq   = (const float*)d_in[2];
    const float* Wk   = (const float*)d_in[3];
    const float* bk   = (const float*)d_in[4];
    const float* Wv   = (const float*)d_in[5];
    const float* bv   = (const float*)d_in[6];
    const float* Wo   = (const float*)d_in[7];
    const float* bo   = (const float*)d_in[8];
    const float* ln_g = (const float*)d_in[9];
    const float* ln_b = (const float*)d_in[10];
    float* out = (float*)d_out;

    float* yp;
    __half *xh, *wh, *qh, *kh, *vh, *ch;
    cudaGetSymbolAddress((void**)&yp, g_y);
    cudaGetSymbolAddress((void**)&xh, g_xh);
    cudaGetSymbolAddress((void**)&wh, g_wh);
    cudaGetSymbolAddress((void**)&qh, g_qh);
    cudaGetSymbolAddress((void**)&kh, g_kh);
    cudaGetSymbolAddress((void**)&vh, g_vh);
    cudaGetSymbolAddress((void**)&ch, g_ch);

    static bool attr_done = false;
    if (!attr_done) {
        cudaFuncSetAttribute(gemm_qkv, cudaFuncAttributeMaxDynamicSharedMemorySize, 2 * GF_STG);
        cudaFuncSetAttribute(gemm_out, cudaFuncAttributeMaxDynamicSharedMemorySize, 2 * GF_STG);
        cudaFuncSetAttribute(attn_mma, cudaFuncAttributeMaxDynamicSharedMemorySize, 2 * A_STG);
        attr_done = true;
    }

    const int WSZ = Hdim * Hdim;
    xhalf_kernel<<<Mtot * Hdim / 1024, 256>>>(x, xh);
    whalf_kernel<<<WSZ / 1024, 256>>>(Wq, wh + 0 * WSZ);
    whalf_kernel<<<WSZ / 1024, 256>>>(Wk, wh + 1 * WSZ);
    whalf_kernel<<<WSZ / 1024, 256>>>(Wv, wh + 2 * WSZ);
    whalf_kernel<<<WSZ / 1024, 256>>>(Wo, wh + 3 * WSZ);

    gemm_qkv<<<dim3(3 * Hdim / 128, Mtot / 128), 256, 2 * GF_STG>>>(
        xh, wh, bq, bk, bv, qh, kh, vh);

    attn_mma<<<dim3(Slen / 64, NHn, Bsz), 128, 2 * A_STG>>>(qh, kh, vh, ch);

    gemm_out<<<dim3(Hdim / 128, Mtot / 128), 256, 2 * GF_STG>>>(
        ch, wh + 3 * WSZ, bo, x, yp);

    ln_kernel<<<Mtot, 256>>>(yp, ln_g, ln_b, out);
}